// round 9
// baseline (speedup 1.0000x reference)
#include <cuda_runtime.h>
#include <math.h>

#define MAXN 100000
#define DM 32
#define RK 16
#define PKW 16       // padded row: 16 int32 = 64 B (32 int8 mean + 16 int8 std + 16 B zero)
#define QS 32.0f     // int8 quantization scale
#define QS2INV (1.0f / (32.0f * 32.0f))
#define GRAM_BLKS 296
#define TP 132       // padded transposed tile stride (128 rows + 4)

// Scratch (no allocations allowed). Invariant: g_deg/g_acc/g_gram are ZERO
// on entry to kernel_launch (zero-init at load; re-zeroed at end of k_final).
__device__ int    g_deg[MAXN];
__device__ float  g_dinv[MAXN];
__device__ double g_acc[3];          // 0: sum(z_mean^2), 1: D, 2: selfloop w sum
__device__ float  g_gram[RK * RK];   // z_std^T z_std (float atomics)
__device__ __align__(16) int g_pack[MAXN * PKW];  // 6.4 MB int8 rows

// ---------------------------------------------------------------------------
// Fused: blocks [0,GRAM_BLKS) compute Gram = z_std^T z_std;
//        blocks [GRAM_BLKS,..) compute the degree histogram (independent work).
__global__ void __launch_bounds__(256) k_deg_gram(
    const float* __restrict__ zs, const int* __restrict__ ei, int N, int E) {
    if (blockIdx.x < GRAM_BLKS) {
        // ---- Gram part: transposed padded tile, LDS.128 inner loop ----
        __shared__ float sh[RK * TP];          // [col][row], pad 132
        int a = threadIdx.x >> 4, b = threadIdx.x & 15;
        float acc = 0.0f;
        for (int row0 = blockIdx.x * 128; row0 < N; row0 += GRAM_BLKS * 128) {
            __syncthreads();
            // load 128 rows x 16 cols, scatter-transpose into sh[col][row]
            for (int t = threadIdx.x; t < 512; t += 256) {
                int row = t >> 2;              // 0..127
                int cb = (t & 3) * 4;          // col base 0,4,8,12
                int grow = row0 + row;
                float4 v = make_float4(0.f, 0.f, 0.f, 0.f);
                if (grow < N) v = ((const float4*)zs)[(size_t)grow * 4 + (t & 3)];
                sh[(cb + 0) * TP + row] = v.x;
                sh[(cb + 1) * TP + row] = v.y;
                sh[(cb + 2) * TP + row] = v.z;
                sh[(cb + 3) * TP + row] = v.w;
            }
            __syncthreads();
            const float4* ca = (const float4*)(sh + a * TP);
            const float4* cb4 = (const float4*)(sh + b * TP);
#pragma unroll 8
            for (int i = 0; i < 32; i++) {
                float4 va = ca[i];
                float4 vb = cb4[i];
                acc += va.x * vb.x + va.y * vb.y + va.z * vb.z + va.w * vb.w;
            }
        }
        atomicAdd(&g_gram[threadIdx.x], acc);
    } else {
        // ---- degree histogram part (int4-vectorized) ----
        int nb = gridDim.x - GRAM_BLKS;
        int i0 = (blockIdx.x - GRAM_BLKS) * blockDim.x + threadIdx.x;
        int n4 = E >> 2;
        for (int i = i0; i < n4; i += nb * blockDim.x) {
            int4 v = ((const int4*)ei)[i];
            atomicAdd(&g_deg[v.x], 1);
            atomicAdd(&g_deg[v.y], 1);
            atomicAdd(&g_deg[v.z], 1);
            atomicAdd(&g_deg[v.w], 1);
        }
        if (i0 < (E & 3)) atomicAdd(&g_deg[ei[n4 * 4 + i0]], 1);
    }
}

// ---------------------------------------------------------------------------
__device__ __forceinline__ int q8(float v) {
    int q = __float2int_rn(v * QS);
    return max(-127, min(127, q));
}
__device__ __forceinline__ int q8x4(float4 v) {
    int a = q8(v.x), b = q8(v.y), c = q8(v.z), d = q8(v.w);
    return (a & 0xFF) | ((b & 0xFF) << 8) | ((c & 0xFF) << 16) | ((d & 0xFF) << 24);
}

// Pack per-node scaled rows to int8 (64B padded); fuse dinv + sum(z_mean^2).
// 8 threads per node row; 256 threads -> 32 rows/block.
__global__ void __launch_bounds__(256) k_pack(
    const float* __restrict__ zm, const float* __restrict__ zs, int N) {
    const float MS = 0.17677669529663687f;  // 1/sqrt(32)
    int sub = threadIdx.x & 7;
    int row = blockIdx.x * 32 + (threadIdx.x >> 3);

    float acc = 0.0f;
    if (row < N) {
        int d = g_deg[row];
        float di = (d > 0) ? rsqrtf((float)d) : 0.0f;
        if (sub == 0) g_dinv[row] = di;
        float ms = di * MS;
        float4 mv = ((const float4*)(zm + (size_t)row * DM))[sub];
        acc = mv.x * mv.x + mv.y * mv.y + mv.z * mv.z + mv.w * mv.w;
        float4 mq = make_float4(mv.x * ms, mv.y * ms, mv.z * ms, mv.w * ms);
        g_pack[(size_t)row * PKW + sub] = q8x4(mq);
        if (sub < 4) {
            float4 sv = ((const float4*)(zs + (size_t)row * RK))[sub];
            float4 sq = make_float4(sv.x * di, sv.y * di, sv.z * di, sv.w * di);
            g_pack[(size_t)row * PKW + 8 + sub] = q8x4(sq);
        } else {
            g_pack[(size_t)row * PKW + 8 + sub] = 0;
        }
    }
    // block reduce sumsq
    for (int o = 16; o; o >>= 1) acc += __shfl_xor_sync(0xffffffffu, acc, o);
    __shared__ float sh[8];
    int w = threadIdx.x >> 5, l = threadIdx.x & 31;
    if (l == 0) sh[w] = acc;
    __syncthreads();
    if (threadIdx.x == 0) {
        float s = 0.0f;
        for (int i = 0; i < 8; i++) s += sh[i];
        atomicAdd(&g_acc[0], (double)s);
    }
}

// ---------------------------------------------------------------------------
__device__ __forceinline__ void edge_dp(int r, int c, int sub, int& accI,
                                        float& aself) {
    int4 ua = __ldg((const int4*)(g_pack + (size_t)r * PKW) + sub);
    int4 ub = __ldg((const int4*)(g_pack + (size_t)c * PKW) + sub);
    accI = __dp4a(ua.x, ub.x, accI);
    accI = __dp4a(ua.y, ub.y, accI);
    accI = __dp4a(ua.z, ub.z, accI);
    accI = __dp4a(ua.w, ub.w, accI);
    if (sub == 3 && r == c) {
        float di = g_dinv[r];
        aself += di * di;
    }
}

// Dominant kernel: per-edge int8 dot via dp4a. 4 lanes/edge, 16B each.
// 4 edges in flight (indices loaded up front, 4 independent gather chains).
__global__ void __launch_bounds__(256) k_edges(const int* __restrict__ ei, int E) {
    int tid = blockIdx.x * blockDim.x + threadIdx.x;
    int sub = threadIdx.x & 3;
    int gid = tid >> 2;
    int gstride = (gridDim.x * blockDim.x) >> 2;

    int acc0 = 0, acc1 = 0, acc2 = 0, acc3 = 0;
    float aself = 0.0f;

    int iters = (E + gstride - 1) / gstride;
    int U = iters - 1;                 // unguarded iterations
    int it = 0;
    for (; it + 3 < U; it += 4) {
        int e0 = gid + it * gstride;
        int e1 = e0 + gstride, e2 = e1 + gstride, e3 = e2 + gstride;
        int r0 = __ldg(ei + e0), c0 = __ldg(ei + (size_t)E + e0);
        int r1 = __ldg(ei + e1), c1 = __ldg(ei + (size_t)E + e1);
        int r2 = __ldg(ei + e2), c2 = __ldg(ei + (size_t)E + e2);
        int r3 = __ldg(ei + e3), c3 = __ldg(ei + (size_t)E + e3);
        edge_dp(r0, c0, sub, acc0, aself);
        edge_dp(r1, c1, sub, acc1, aself);
        edge_dp(r2, c2, sub, acc2, aself);
        edge_dp(r3, c3, sub, acc3, aself);
    }
    for (; it < U; it++) {
        int e = gid + it * gstride;
        int r = __ldg(ei + e), c = __ldg(ei + (size_t)E + e);
        edge_dp(r, c, sub, acc0, aself);
    }
    {                                  // guarded tail
        int e = gid + U * gstride;
        if (e < E) {
            int r = __ldg(ei + e), c = __ldg(ei + (size_t)E + e);
            edge_dp(r, c, sub, acc1, aself);
        }
    }

    float accD = (float)((acc0 + acc1) + (acc2 + acc3)) * QS2INV;

    // block reduce
    for (int o = 16; o; o >>= 1) {
        accD += __shfl_xor_sync(0xffffffffu, accD, o);
        aself += __shfl_xor_sync(0xffffffffu, aself, o);
    }
    __shared__ float s0[8], s1[8];
    int w = threadIdx.x >> 5, l = threadIdx.x & 31;
    if (l == 0) { s0[w] = accD; s1[w] = aself; }
    __syncthreads();
    if (threadIdx.x == 0) {
        float A = 0.f, B = 0.f;
        for (int i = 0; i < 8; i++) { A += s0[i]; B += s1[i]; }
        atomicAdd(&g_acc[1], (double)A);
        atomicAdd(&g_acc[2], (double)B);
    }
}

// finalize + state reset. Block 0: float Cholesky logdet, write result, then
// zero g_acc/g_gram (after syncthreads). Blocks 1..: zero g_deg for next replay.
__global__ void k_final(float* out, int N) {
    if (blockIdx.x == 0) {
        if (threadIdx.x == 0) {
            float M[RK][RK];
            float tr = 0.0f;
            for (int i = 0; i < RK; i++) {
                for (int j = 0; j < RK; j++)
                    M[i][j] = g_gram[i * RK + j] + (i == j ? 1.0f : 0.0f);
                tr += g_gram[i * RK + i];  // sum(z_std^2) = trace(Gram)
            }
            float logdet = 0.0f;
            for (int k = 0; k < RK; k++) {
                float d = M[k][k];
                for (int j = 0; j < k; j++) d -= M[k][j] * M[k][j];
                float lkk = sqrtf(d);
                logdet += __logf(lkk);
                float inv = 1.0f / lkk;
                M[k][k] = lkk;
                for (int i = k + 1; i < RK; i++) {
                    float s = M[i][k];
                    for (int j = 0; j < k; j++) s -= M[i][j] * M[k][j];
                    M[i][k] = s * inv;
                }
            }
            logdet *= 2.0f;

            double trace_L = (double)N - g_acc[2];
            double res = (g_acc[0] / (double)DM + (double)tr + trace_L
                          - g_acc[1] - (double)logdet) / (2.0 * (double)N);
            out[0] = (float)res;
        }
        __syncthreads();   // result consumed before reset
        if (threadIdx.x < RK * RK) g_gram[threadIdx.x] = 0.0f;
        if (threadIdx.x < 3) g_acc[threadIdx.x] = 0.0;
        if (threadIdx.x < N) g_deg[threadIdx.x] = 0;
    } else {
        int i = blockIdx.x * 256 + threadIdx.x;
        if (i < N) g_deg[i] = 0;
    }
}

// ---------------------------------------------------------------------------
extern "C" void kernel_launch(void* const* d_in, const int* in_sizes, int n_in,
                              void* d_out, int out_size) {
    const float* zm = (const float*)d_in[0];
    const float* zs = (const float*)d_in[1];
    const int*   ei = (const int*)d_in[2];

    int N = in_sizes[0] / DM;
    int E = in_sizes[2] / 2;

    k_deg_gram<<<GRAM_BLKS + 1264, 256>>>(zs, ei, N, E);
    k_pack<<<(N + 31) / 32, 256>>>(zm, zs, N);
    k_edges<<<888, 256>>>(ei, E);    // 148 SMs x 6 CTAs -> one exact wave
    k_final<<<(N + 255) / 256, 256>>>((float*)d_out, N);
}

// round 10
// speedup vs baseline: 1.1207x; 1.1207x over previous
#include <cuda_runtime.h>
#include <math.h>

#define MAXN 100000
#define DM 32
#define RK 16
#define PKW 16       // padded row: 16 int32 = 64 B (32 int8 mean + 16 int8 std + 16 B zero)
#define QS 32.0f     // int8 quantization scale
#define QS2INV (1.0f / (32.0f * 32.0f))
#define GRAM_BLKS 296
#define TP 132       // padded transposed tile stride (128 rows + 4)

// Scratch (no allocations allowed). Invariant: g_deg/g_acc/g_gram are ZERO
// on entry to kernel_launch (zero-init at load; re-zeroed at end of k_final).
__device__ int    g_deg[MAXN];
__device__ float  g_dinv[MAXN];
__device__ double g_acc[3];          // 0: sum(z_mean^2), 1: D, 2: selfloop w sum
__device__ float  g_gram[RK * RK];   // z_std^T z_std (float atomics)
__device__ __align__(16) int g_pack[MAXN * PKW];  // 6.4 MB int8 rows

// ---------------------------------------------------------------------------
// Fused: blocks [0,GRAM_BLKS) compute Gram = z_std^T z_std;
//        blocks [GRAM_BLKS,..) compute the degree histogram (independent work).
__global__ void __launch_bounds__(256) k_deg_gram(
    const float* __restrict__ zs, const int* __restrict__ ei, int N, int E) {
    if (blockIdx.x < GRAM_BLKS) {
        // ---- Gram part: transposed padded tile, LDS.128 inner loop ----
        __shared__ float sh[RK * TP];          // [col][row], pad 132
        int a = threadIdx.x >> 4, b = threadIdx.x & 15;
        float acc = 0.0f;
        for (int row0 = blockIdx.x * 128; row0 < N; row0 += GRAM_BLKS * 128) {
            __syncthreads();
            // load 128 rows x 16 cols, scatter-transpose into sh[col][row]
            for (int t = threadIdx.x; t < 512; t += 256) {
                int row = t >> 2;              // 0..127
                int cb = (t & 3) * 4;          // col base 0,4,8,12
                int grow = row0 + row;
                float4 v = make_float4(0.f, 0.f, 0.f, 0.f);
                if (grow < N) v = ((const float4*)zs)[(size_t)grow * 4 + (t & 3)];
                sh[(cb + 0) * TP + row] = v.x;
                sh[(cb + 1) * TP + row] = v.y;
                sh[(cb + 2) * TP + row] = v.z;
                sh[(cb + 3) * TP + row] = v.w;
            }
            __syncthreads();
            const float4* ca = (const float4*)(sh + a * TP);
            const float4* cb4 = (const float4*)(sh + b * TP);
#pragma unroll 8
            for (int i = 0; i < 32; i++) {
                float4 va = ca[i];
                float4 vb = cb4[i];
                acc += va.x * vb.x + va.y * vb.y + va.z * vb.z + va.w * vb.w;
            }
        }
        atomicAdd(&g_gram[threadIdx.x], acc);
    } else {
        // ---- degree histogram part (int4-vectorized) ----
        int nb = gridDim.x - GRAM_BLKS;
        int i0 = (blockIdx.x - GRAM_BLKS) * blockDim.x + threadIdx.x;
        int n4 = E >> 2;
        for (int i = i0; i < n4; i += nb * blockDim.x) {
            int4 v = ((const int4*)ei)[i];
            atomicAdd(&g_deg[v.x], 1);
            atomicAdd(&g_deg[v.y], 1);
            atomicAdd(&g_deg[v.z], 1);
            atomicAdd(&g_deg[v.w], 1);
        }
        if (i0 < (E & 3)) atomicAdd(&g_deg[ei[n4 * 4 + i0]], 1);
    }
}

// ---------------------------------------------------------------------------
__device__ __forceinline__ int q8(float v) {
    int q = __float2int_rn(v * QS);
    return max(-127, min(127, q));
}
__device__ __forceinline__ int q8x4(float4 v) {
    int a = q8(v.x), b = q8(v.y), c = q8(v.z), d = q8(v.w);
    return (a & 0xFF) | ((b & 0xFF) << 8) | ((c & 0xFF) << 16) | ((d & 0xFF) << 24);
}

// Pack per-node scaled rows to int8 (64B padded); fuse dinv + sum(z_mean^2).
// 8 threads per node row; 256 threads -> 32 rows/block.
__global__ void __launch_bounds__(256) k_pack(
    const float* __restrict__ zm, const float* __restrict__ zs, int N) {
    const float MS = 0.17677669529663687f;  // 1/sqrt(32)
    int sub = threadIdx.x & 7;
    int row = blockIdx.x * 32 + (threadIdx.x >> 3);

    float acc = 0.0f;
    if (row < N) {
        int d = g_deg[row];
        float di = (d > 0) ? rsqrtf((float)d) : 0.0f;
        if (sub == 0) g_dinv[row] = di;
        float ms = di * MS;
        float4 mv = ((const float4*)(zm + (size_t)row * DM))[sub];
        acc = mv.x * mv.x + mv.y * mv.y + mv.z * mv.z + mv.w * mv.w;
        float4 mq = make_float4(mv.x * ms, mv.y * ms, mv.z * ms, mv.w * ms);
        g_pack[(size_t)row * PKW + sub] = q8x4(mq);
        if (sub < 4) {
            float4 sv = ((const float4*)(zs + (size_t)row * RK))[sub];
            float4 sq = make_float4(sv.x * di, sv.y * di, sv.z * di, sv.w * di);
            g_pack[(size_t)row * PKW + 8 + sub] = q8x4(sq);
        } else {
            g_pack[(size_t)row * PKW + 8 + sub] = 0;
        }
    }
    // block reduce sumsq
    for (int o = 16; o; o >>= 1) acc += __shfl_xor_sync(0xffffffffu, acc, o);
    __shared__ float sh[8];
    int w = threadIdx.x >> 5, l = threadIdx.x & 31;
    if (l == 0) sh[w] = acc;
    __syncthreads();
    if (threadIdx.x == 0) {
        float s = 0.0f;
        for (int i = 0; i < 8; i++) s += sh[i];
        atomicAdd(&g_acc[0], (double)s);
    }
}

// ---------------------------------------------------------------------------
__device__ __forceinline__ void edge_dp(int r, int c, int sub, int& accI,
                                        float& aself) {
    int4 ua = __ldg((const int4*)(g_pack + (size_t)r * PKW) + sub);
    int4 ub = __ldg((const int4*)(g_pack + (size_t)c * PKW) + sub);
    accI = __dp4a(ua.x, ub.x, accI);
    accI = __dp4a(ua.y, ub.y, accI);
    accI = __dp4a(ua.z, ub.z, accI);
    accI = __dp4a(ua.w, ub.w, accI);
    if (sub == 3 && r == c) {
        float di = g_dinv[r];
        aself += di * di;
    }
}

// Dominant kernel: per-edge int8 dot via dp4a. 4 lanes/edge, 16B each.
// 4 edges in flight (indices loaded up front, 4 independent gather chains).
__global__ void __launch_bounds__(256) k_edges(const int* __restrict__ ei, int E) {
    int tid = blockIdx.x * blockDim.x + threadIdx.x;
    int sub = threadIdx.x & 3;
    int gid = tid >> 2;
    int gstride = (gridDim.x * blockDim.x) >> 2;

    int acc0 = 0, acc1 = 0, acc2 = 0, acc3 = 0;
    float aself = 0.0f;

    int iters = (E + gstride - 1) / gstride;
    int U = iters - 1;                 // unguarded iterations
    int it = 0;
    for (; it + 3 < U; it += 4) {
        int e0 = gid + it * gstride;
        int e1 = e0 + gstride, e2 = e1 + gstride, e3 = e2 + gstride;
        int r0 = __ldg(ei + e0), c0 = __ldg(ei + (size_t)E + e0);
        int r1 = __ldg(ei + e1), c1 = __ldg(ei + (size_t)E + e1);
        int r2 = __ldg(ei + e2), c2 = __ldg(ei + (size_t)E + e2);
        int r3 = __ldg(ei + e3), c3 = __ldg(ei + (size_t)E + e3);
        edge_dp(r0, c0, sub, acc0, aself);
        edge_dp(r1, c1, sub, acc1, aself);
        edge_dp(r2, c2, sub, acc2, aself);
        edge_dp(r3, c3, sub, acc3, aself);
    }
    for (; it < U; it++) {
        int e = gid + it * gstride;
        int r = __ldg(ei + e), c = __ldg(ei + (size_t)E + e);
        edge_dp(r, c, sub, acc0, aself);
    }
    {                                  // guarded tail
        int e = gid + U * gstride;
        if (e < E) {
            int r = __ldg(ei + e), c = __ldg(ei + (size_t)E + e);
            edge_dp(r, c, sub, acc1, aself);
        }
    }

    float accD = (float)((acc0 + acc1) + (acc2 + acc3)) * QS2INV;

    // block reduce
    for (int o = 16; o; o >>= 1) {
        accD += __shfl_xor_sync(0xffffffffu, accD, o);
        aself += __shfl_xor_sync(0xffffffffu, aself, o);
    }
    __shared__ float s0[8], s1[8];
    int w = threadIdx.x >> 5, l = threadIdx.x & 31;
    if (l == 0) { s0[w] = accD; s1[w] = aself; }
    __syncthreads();
    if (threadIdx.x == 0) {
        float A = 0.f, B = 0.f;
        for (int i = 0; i < 8; i++) { A += s0[i]; B += s1[i]; }
        atomicAdd(&g_acc[1], (double)A);
        atomicAdd(&g_acc[2], (double)B);
    }
}

// finalize + state reset. Block 0 warp 0: cooperative Cholesky in SHARED
// memory (16 threads, one per row) -- no local-memory spill, ~2K cycles.
// Blocks 1..: zero g_deg for next replay.
__global__ void k_final(float* out, int N) {
    if (blockIdx.x == 0) {
        __shared__ float M[RK][RK + 1];
        int tid = threadIdx.x;
        // load I + Gram (256 threads, one element each)
        if (tid < RK * RK) {
            int i = tid >> 4, j = tid & 15;
            M[i][j] = g_gram[tid] + (i == j ? 1.0f : 0.0f);
        }
        __syncthreads();

        if (tid < 32) {
            int i = tid & 15;   // row owned by this thread (threads 16-31 idle)
            bool own = (tid < RK);
#pragma unroll
            for (int k = 0; k < RK; k++) {
                if (own && i == k) M[k][k] = sqrtf(M[k][k]);
                __syncwarp();
                if (own && i > k) M[i][k] /= M[k][k];
                __syncwarp();
                if (own && i > k) {
                    float lik = M[i][k];
                    for (int j = k + 1; j <= i; j++)
                        M[i][j] -= lik * M[j][k];
                }
                __syncwarp();
            }
            if (tid == 0) {
                float logdet = 0.0f, tr = 0.0f;
#pragma unroll
                for (int k = 0; k < RK; k++) {
                    logdet += __logf(M[k][k]);
                    tr += g_gram[k * RK + k];   // sum(z_std^2) = trace(Gram)
                }
                logdet *= 2.0f;
                double trace_L = (double)N - g_acc[2];
                double res = (g_acc[0] / (double)DM + (double)tr + trace_L
                              - g_acc[1] - (double)logdet) / (2.0 * (double)N);
                out[0] = (float)res;
            }
        }
        __syncthreads();   // result written before reset
        if (tid < RK * RK) g_gram[tid] = 0.0f;
        if (tid < 3) g_acc[tid] = 0.0;
        if (tid < N) g_deg[tid] = 0;
    } else {
        int i = blockIdx.x * 256 + threadIdx.x;
        if (i < N) g_deg[i] = 0;
    }
}

// ---------------------------------------------------------------------------
extern "C" void kernel_launch(void* const* d_in, const int* in_sizes, int n_in,
                              void* d_out, int out_size) {
    const float* zm = (const float*)d_in[0];
    const float* zs = (const float*)d_in[1];
    const int*   ei = (const int*)d_in[2];

    int N = in_sizes[0] / DM;
    int E = in_sizes[2] / 2;

    k_deg_gram<<<GRAM_BLKS + 1264, 256>>>(zs, ei, N, E);
    k_pack<<<(N + 31) / 32, 256>>>(zm, zs, N);
    k_edges<<<888, 256>>>(ei, E);    // 148 SMs x 6 CTAs -> one exact wave
    k_final<<<(N + 255) / 256, 256>>>((float*)d_out, N);
}

// round 11
// speedup vs baseline: 1.2649x; 1.1287x over previous
#include <cuda_runtime.h>
#include <math.h>

#define MAXN 100000
#define DM 32
#define RK 16
#define PKW 16       // padded row: 16 int32 = 64 B (32 int8 mean + 16 int8 std + 16 B zero)
#define QS 32.0f     // int8 quantization scale
#define QS2INV (1.0f / (32.0f * 32.0f))
#define GRAM_BLKS 296
#define TP 132       // padded transposed tile stride (128 rows + 4)

// Scratch (no allocations allowed). Invariant: g_deg/g_acc/g_gram are ZERO
// on entry to kernel_launch (zero-init at load; re-zeroed at end of k_final).
__device__ int    g_deg[MAXN];
__device__ float  g_dinv[MAXN];
__device__ double g_acc[3];          // 0: sum(z_mean^2), 1: D, 2: selfloop w sum
__device__ float  g_gram[RK * RK];   // z_std^T z_std (float atomics)
__device__ __align__(16) int g_pack[MAXN * PKW];  // 6.4 MB int8 rows

// ---------------------------------------------------------------------------
// Fused: blocks [0,GRAM_BLKS) compute Gram = z_std^T z_std;
//        blocks [GRAM_BLKS,..) compute the degree histogram (independent work).
__global__ void __launch_bounds__(256) k_deg_gram(
    const float* __restrict__ zs, const int* __restrict__ ei, int N, int E) {
    if (blockIdx.x < GRAM_BLKS) {
        // ---- Gram part: transposed padded tile, LDS.128 inner loop ----
        __shared__ float sh[RK * TP];          // [col][row], pad 132
        int a = threadIdx.x >> 4, b = threadIdx.x & 15;
        float acc = 0.0f;
        for (int row0 = blockIdx.x * 128; row0 < N; row0 += GRAM_BLKS * 128) {
            __syncthreads();
            // load 128 rows x 16 cols, scatter-transpose into sh[col][row]
            for (int t = threadIdx.x; t < 512; t += 256) {
                int row = t >> 2;              // 0..127
                int cb = (t & 3) * 4;          // col base 0,4,8,12
                int grow = row0 + row;
                float4 v = make_float4(0.f, 0.f, 0.f, 0.f);
                if (grow < N) v = ((const float4*)zs)[(size_t)grow * 4 + (t & 3)];
                sh[(cb + 0) * TP + row] = v.x;
                sh[(cb + 1) * TP + row] = v.y;
                sh[(cb + 2) * TP + row] = v.z;
                sh[(cb + 3) * TP + row] = v.w;
            }
            __syncthreads();
            const float4* ca = (const float4*)(sh + a * TP);
            const float4* cb4 = (const float4*)(sh + b * TP);
#pragma unroll 8
            for (int i = 0; i < 32; i++) {
                float4 va = ca[i];
                float4 vb = cb4[i];
                acc += va.x * vb.x + va.y * vb.y + va.z * vb.z + va.w * vb.w;
            }
        }
        atomicAdd(&g_gram[threadIdx.x], acc);
    } else {
        // ---- degree histogram part (int4-vectorized) ----
        int nb = gridDim.x - GRAM_BLKS;
        int i0 = (blockIdx.x - GRAM_BLKS) * blockDim.x + threadIdx.x;
        int n4 = E >> 2;
        for (int i = i0; i < n4; i += nb * blockDim.x) {
            int4 v = ((const int4*)ei)[i];
            atomicAdd(&g_deg[v.x], 1);
            atomicAdd(&g_deg[v.y], 1);
            atomicAdd(&g_deg[v.z], 1);
            atomicAdd(&g_deg[v.w], 1);
        }
        if (i0 < (E & 3)) atomicAdd(&g_deg[ei[n4 * 4 + i0]], 1);
    }
}

// ---------------------------------------------------------------------------
__device__ __forceinline__ int q8(float v) {
    int q = __float2int_rn(v * QS);
    return max(-127, min(127, q));
}
__device__ __forceinline__ int q8x4(float4 v) {
    int a = q8(v.x), b = q8(v.y), c = q8(v.z), d = q8(v.w);
    return (a & 0xFF) | ((b & 0xFF) << 8) | ((c & 0xFF) << 16) | ((d & 0xFF) << 24);
}

// Pack per-node scaled rows to int8 (64B padded); fuse dinv + sum(z_mean^2).
// 8 threads per node row; 256 threads -> 32 rows/block.
__global__ void __launch_bounds__(256) k_pack(
    const float* __restrict__ zm, const float* __restrict__ zs, int N) {
    const float MS = 0.17677669529663687f;  // 1/sqrt(32)
    int sub = threadIdx.x & 7;
    int row = blockIdx.x * 32 + (threadIdx.x >> 3);

    float acc = 0.0f;
    if (row < N) {
        int d = g_deg[row];
        float di = (d > 0) ? rsqrtf((float)d) : 0.0f;
        if (sub == 0) g_dinv[row] = di;
        float ms = di * MS;
        float4 mv = ((const float4*)(zm + (size_t)row * DM))[sub];
        acc = mv.x * mv.x + mv.y * mv.y + mv.z * mv.z + mv.w * mv.w;
        float4 mq = make_float4(mv.x * ms, mv.y * ms, mv.z * ms, mv.w * ms);
        g_pack[(size_t)row * PKW + sub] = q8x4(mq);
        if (sub < 4) {
            float4 sv = ((const float4*)(zs + (size_t)row * RK))[sub];
            float4 sq = make_float4(sv.x * di, sv.y * di, sv.z * di, sv.w * di);
            g_pack[(size_t)row * PKW + 8 + sub] = q8x4(sq);
        } else {
            g_pack[(size_t)row * PKW + 8 + sub] = 0;
        }
    }
    // block reduce sumsq
    for (int o = 16; o; o >>= 1) acc += __shfl_xor_sync(0xffffffffu, acc, o);
    __shared__ float sh[8];
    int w = threadIdx.x >> 5, l = threadIdx.x & 31;
    if (l == 0) sh[w] = acc;
    __syncthreads();
    if (threadIdx.x == 0) {
        float s = 0.0f;
        for (int i = 0; i < 8; i++) s += sh[i];
        atomicAdd(&g_acc[0], (double)s);
    }
}

// ---------------------------------------------------------------------------
__device__ __forceinline__ void edge_dp(int r, int c, int sub, int& accI,
                                        float& aself) {
    int4 ua = __ldg((const int4*)(g_pack + (size_t)r * PKW) + sub);
    int4 ub = __ldg((const int4*)(g_pack + (size_t)c * PKW) + sub);
    accI = __dp4a(ua.x, ub.x, accI);
    accI = __dp4a(ua.y, ub.y, accI);
    accI = __dp4a(ua.z, ub.z, accI);
    accI = __dp4a(ua.w, ub.w, accI);
    if (sub == 3 && r == c) {
        float di = g_dinv[r];
        aself += di * di;
    }
}

// Dominant kernel: per-edge int8 dot via dp4a. 4 lanes/edge, 16B each.
// 4 edges in flight (indices loaded up front, 4 independent gather chains).
__global__ void __launch_bounds__(256) k_edges(const int* __restrict__ ei, int E) {
    int tid = blockIdx.x * blockDim.x + threadIdx.x;
    int sub = threadIdx.x & 3;
    int gid = tid >> 2;
    int gstride = (gridDim.x * blockDim.x) >> 2;

    int acc0 = 0, acc1 = 0, acc2 = 0, acc3 = 0;
    float aself = 0.0f;

    int iters = (E + gstride - 1) / gstride;
    int U = iters - 1;                 // unguarded iterations
    int it = 0;
    for (; it + 3 < U; it += 4) {
        int e0 = gid + it * gstride;
        int e1 = e0 + gstride, e2 = e1 + gstride, e3 = e2 + gstride;
        int r0 = __ldg(ei + e0), c0 = __ldg(ei + (size_t)E + e0);
        int r1 = __ldg(ei + e1), c1 = __ldg(ei + (size_t)E + e1);
        int r2 = __ldg(ei + e2), c2 = __ldg(ei + (size_t)E + e2);
        int r3 = __ldg(ei + e3), c3 = __ldg(ei + (size_t)E + e3);
        edge_dp(r0, c0, sub, acc0, aself);
        edge_dp(r1, c1, sub, acc1, aself);
        edge_dp(r2, c2, sub, acc2, aself);
        edge_dp(r3, c3, sub, acc3, aself);
    }
    for (; it < U; it++) {
        int e = gid + it * gstride;
        int r = __ldg(ei + e), c = __ldg(ei + (size_t)E + e);
        edge_dp(r, c, sub, acc0, aself);
    }
    {                                  // guarded tail
        int e = gid + U * gstride;
        if (e < E) {
            int r = __ldg(ei + e), c = __ldg(ei + (size_t)E + e);
            edge_dp(r, c, sub, acc1, aself);
        }
    }

    float accD = (float)((acc0 + acc1) + (acc2 + acc3)) * QS2INV;

    // block reduce
    for (int o = 16; o; o >>= 1) {
        accD += __shfl_xor_sync(0xffffffffu, accD, o);
        aself += __shfl_xor_sync(0xffffffffu, aself, o);
    }
    __shared__ float s0[8], s1[8];
    int w = threadIdx.x >> 5, l = threadIdx.x & 31;
    if (l == 0) { s0[w] = accD; s1[w] = aself; }
    __syncthreads();
    if (threadIdx.x == 0) {
        float A = 0.f, B = 0.f;
        for (int i = 0; i < 8; i++) { A += s0[i]; B += s1[i]; }
        atomicAdd(&g_acc[1], (double)A);
        atomicAdd(&g_acc[2], (double)B);
    }
}

// finalize + state reset. Block 0 warp 0: ALL-REGISTER shuffle Cholesky
// (thread i holds row i in 16 regs, fully unrolled -> no spill, no smem).
// Blocks 1..: int4-vectorized zero of g_deg for next replay.
__global__ void __launch_bounds__(256) k_final(float* out, int N) {
    if (blockIdx.x == 0) {
        int tid = threadIdx.x;
        if (tid < 32) {
            int i = tid;                       // lanes 16-31: inert mirrors
            // read accumulators early (reset happens after __syncthreads)
            double a0 = g_acc[0], a1 = g_acc[1], a2 = g_acc[2];

            float m[RK];
            float tr = 0.0f;
#pragma unroll
            for (int j = 0; j < RK; j++) {
                float g = (i < RK) ? g_gram[i * RK + j] : 0.0f;
                m[j] = g + (i == j ? 1.0f : 0.0f);
                if (i == j) tr = g;            // diag element -> trace term
            }
            // trace = sum over lanes 0..15 of per-lane diag
            for (int o = 8; o; o >>= 1) tr += __shfl_xor_sync(0xffffffffu, tr, o);

            float logdet = 0.0f;
#pragma unroll
            for (int k = 0; k < RK; k++) {
                float lkk = sqrtf(__shfl_sync(0xffffffffu, m[k], k));
                logdet += __logf(lkk);
                if (i == k) m[k] = lkk;
                else if (i > k) m[k] /= lkk;   // l_ik
#pragma unroll
                for (int j = k + 1; j < RK; j++) {
                    float ljk = __shfl_sync(0xffffffffu, m[k], j);
                    if (i >= j) m[j] -= m[k] * ljk;
                }
            }
            logdet *= 2.0f;

            if (tid == 0) {
                double trace_L = (double)N - a2;
                double res = (a0 / (double)DM + (double)tr + trace_L
                              - a1 - (double)logdet) / (2.0 * (double)N);
                out[0] = (float)res;
            }
        }
        __syncthreads();   // result + early reads done before reset
        if (tid < RK * RK) g_gram[tid] = 0.0f;
        if (tid < 3) g_acc[tid] = 0.0;
    } else {
        // zero g_deg: int4 stores, blocks 1..ceil(N/4/256)
        int i4 = (blockIdx.x - 1) * 256 + threadIdx.x;
        if (i4 < (N >> 2)) ((int4*)g_deg)[i4] = make_int4(0, 0, 0, 0);
        int t = (N & ~3) + i4 - ((N >> 2) / 1) * 0;  // tail
        if (blockIdx.x == 1 && threadIdx.x < (N & 3)) g_deg[(N & ~3) + threadIdx.x] = 0;
    }
}

// ---------------------------------------------------------------------------
extern "C" void kernel_launch(void* const* d_in, const int* in_sizes, int n_in,
                              void* d_out, int out_size) {
    const float* zm = (const float*)d_in[0];
    const float* zs = (const float*)d_in[1];
    const int*   ei = (const int*)d_in[2];

    int N = in_sizes[0] / DM;
    int E = in_sizes[2] / 2;

    k_deg_gram<<<GRAM_BLKS + 1264, 256>>>(zs, ei, N, E);
    k_pack<<<(N + 31) / 32, 256>>>(zm, zs, N);
    k_edges<<<888, 256>>>(ei, E);    // 148 SMs x 6 CTAs -> one exact wave
    k_final<<<1 + (N / 4 + 255) / 256, 256>>>((float*)d_out, N);
}

// round 12
// speedup vs baseline: 1.3799x; 1.0909x over previous
#include <cuda_runtime.h>
#include <math.h>

#define MAXN 100000
#define DM 32
#define RK 16
#define PKW 16       // padded row: 16 int32 = 64 B (32 int8 mean + 16 int8 std + 16 B zero)
#define QS 32.0f     // int8 quantization scale
#define QS2INV (1.0f / (32.0f * 32.0f))
#define GRAM_BLKS 296
#define TP 132       // padded transposed tile stride (128 rows + 4)
#define EDGE_BLKS 888

// Scratch (no allocations allowed). Invariant: g_deg/g_acc/g_gram/g_misc are
// ZERO at entry (zero-init at load; re-zeroed inside the pipeline each run).
__device__ int    g_deg[MAXN];
__device__ float  g_dinv[MAXN];
__device__ double g_acc[3];          // 0: sum(z_mean^2), 1: D, 2: selfloop w sum
__device__ float  g_gram[RK * RK];   // z_std^T z_std (float atomics)
__device__ float  g_misc[2];         // 0: logdet, 1: trace(Gram)
__device__ __align__(16) int g_pack[MAXN * PKW];  // 6.4 MB int8 rows

// ---------------------------------------------------------------------------
// Fused: blocks [0,GRAM_BLKS) compute Gram = z_std^T z_std;
//        blocks [GRAM_BLKS,..) compute the degree histogram (independent work).
__global__ void __launch_bounds__(256) k_deg_gram(
    const float* __restrict__ zs, const int* __restrict__ ei, int N, int E) {
    if (blockIdx.x < GRAM_BLKS) {
        // ---- Gram part: transposed padded tile, LDS.128 inner loop ----
        __shared__ float sh[RK * TP];          // [col][row], pad 132
        int a = threadIdx.x >> 4, b = threadIdx.x & 15;
        float acc = 0.0f;
        for (int row0 = blockIdx.x * 128; row0 < N; row0 += GRAM_BLKS * 128) {
            __syncthreads();
            for (int t = threadIdx.x; t < 512; t += 256) {
                int row = t >> 2;              // 0..127
                int cb = (t & 3) * 4;          // col base 0,4,8,12
                int grow = row0 + row;
                float4 v = make_float4(0.f, 0.f, 0.f, 0.f);
                if (grow < N) v = ((const float4*)zs)[(size_t)grow * 4 + (t & 3)];
                sh[(cb + 0) * TP + row] = v.x;
                sh[(cb + 1) * TP + row] = v.y;
                sh[(cb + 2) * TP + row] = v.z;
                sh[(cb + 3) * TP + row] = v.w;
            }
            __syncthreads();
            const float4* ca = (const float4*)(sh + a * TP);
            const float4* cb4 = (const float4*)(sh + b * TP);
#pragma unroll 8
            for (int i = 0; i < 32; i++) {
                float4 va = ca[i];
                float4 vb = cb4[i];
                acc += va.x * vb.x + va.y * vb.y + va.z * vb.z + va.w * vb.w;
            }
        }
        atomicAdd(&g_gram[threadIdx.x], acc);
    } else {
        // ---- degree histogram part (int4-vectorized) ----
        int nb = gridDim.x - GRAM_BLKS;
        int i0 = (blockIdx.x - GRAM_BLKS) * blockDim.x + threadIdx.x;
        int n4 = E >> 2;
        for (int i = i0; i < n4; i += nb * blockDim.x) {
            int4 v = ((const int4*)ei)[i];
            atomicAdd(&g_deg[v.x], 1);
            atomicAdd(&g_deg[v.y], 1);
            atomicAdd(&g_deg[v.z], 1);
            atomicAdd(&g_deg[v.w], 1);
        }
        if (i0 < (E & 3)) atomicAdd(&g_deg[ei[n4 * 4 + i0]], 1);
    }
}

// ---------------------------------------------------------------------------
__device__ __forceinline__ int q8(float v) {
    int q = __float2int_rn(v * QS);
    return max(-127, min(127, q));
}
__device__ __forceinline__ int q8x4(float4 v) {
    int a = q8(v.x), b = q8(v.y), c = q8(v.z), d = q8(v.w);
    return (a & 0xFF) | ((b & 0xFF) << 8) | ((c & 0xFF) << 16) | ((d & 0xFF) << 24);
}

// Pack per-node scaled rows to int8 (64B padded); fuse dinv + sum(z_mean^2).
// Also RE-ZEROS g_deg (each row's owner, right after the read) so the next
// graph replay starts clean -- no separate reset pass.
__global__ void __launch_bounds__(256) k_pack(
    const float* __restrict__ zm, const float* __restrict__ zs, int N) {
    const float MS = 0.17677669529663687f;  // 1/sqrt(32)
    int sub = threadIdx.x & 7;
    int row = blockIdx.x * 32 + (threadIdx.x >> 3);

    float acc = 0.0f;
    if (row < N) {
        int d = g_deg[row];
        float di = (d > 0) ? rsqrtf((float)d) : 0.0f;
        if (sub == 0) {
            g_dinv[row] = di;
            g_deg[row] = 0;                    // fold the reset in here
        }
        float ms = di * MS;
        float4 mv = ((const float4*)(zm + (size_t)row * DM))[sub];
        acc = mv.x * mv.x + mv.y * mv.y + mv.z * mv.z + mv.w * mv.w;
        float4 mq = make_float4(mv.x * ms, mv.y * ms, mv.z * ms, mv.w * ms);
        g_pack[(size_t)row * PKW + sub] = q8x4(mq);
        if (sub < 4) {
            float4 sv = ((const float4*)(zs + (size_t)row * RK))[sub];
            float4 sq = make_float4(sv.x * di, sv.y * di, sv.z * di, sv.w * di);
            g_pack[(size_t)row * PKW + 8 + sub] = q8x4(sq);
        } else {
            g_pack[(size_t)row * PKW + 8 + sub] = 0;
        }
    }
    // block reduce sumsq
    for (int o = 16; o; o >>= 1) acc += __shfl_xor_sync(0xffffffffu, acc, o);
    __shared__ float sh[8];
    int w = threadIdx.x >> 5, l = threadIdx.x & 31;
    if (l == 0) sh[w] = acc;
    __syncthreads();
    if (threadIdx.x == 0) {
        float s = 0.0f;
        for (int i = 0; i < 8; i++) s += sh[i];
        atomicAdd(&g_acc[0], (double)s);
    }
}

// ---------------------------------------------------------------------------
__device__ __forceinline__ void edge_dp(int r, int c, int sub, int& accI,
                                        float& aself) {
    int4 ua = __ldg((const int4*)(g_pack + (size_t)r * PKW) + sub);
    int4 ub = __ldg((const int4*)(g_pack + (size_t)c * PKW) + sub);
    accI = __dp4a(ua.x, ub.x, accI);
    accI = __dp4a(ua.y, ub.y, accI);
    accI = __dp4a(ua.z, ub.z, accI);
    accI = __dp4a(ua.w, ub.w, accI);
    if (sub == 3 && r == c) {
        float di = g_dinv[r];
        aself += di * di;
    }
}

// Dominant kernel. Blocks [0,EDGE_BLKS): per-edge int8 dp4a dot (4 lanes/edge,
// 4 edges in flight). Block EDGE_BLKS: shuffle-register Cholesky of I+Gram,
// overlapped with the edge pass (gram is final since kernel 1); it stores
// logdet+trace to g_misc and re-zeros g_gram.
__global__ void __launch_bounds__(256) k_edges(const int* __restrict__ ei, int E) {
    if (blockIdx.x >= EDGE_BLKS) {
        int tid = threadIdx.x;
        if (tid < 32) {
            int i = tid;                       // lanes 16-31: inert mirrors
            float m[RK];
            float tr = 0.0f;
#pragma unroll
            for (int j = 0; j < RK; j++) {
                float g = (i < RK) ? g_gram[i * RK + j] : 0.0f;
                m[j] = g + (i == j ? 1.0f : 0.0f);
                if (i == j) tr = g;
            }
            for (int o = 8; o; o >>= 1) tr += __shfl_xor_sync(0xffffffffu, tr, o);

            // logdet = sum log(pivot d_k); rows scaled by rsqrt(d_k) (no div).
            float logdet = 0.0f;
#pragma unroll
            for (int k = 0; k < RK; k++) {
                float d = __shfl_sync(0xffffffffu, m[k], k);
                logdet += __logf(d);
                float rinv = rsqrtf(d);
                if (i >= k) m[k] *= rinv;      // column k of L
#pragma unroll
                for (int j = k + 1; j < RK; j++) {
                    float ljk = __shfl_sync(0xffffffffu, m[k], j);
                    if (i >= j) m[j] -= m[k] * ljk;
                }
            }
            if (tid == 0) {
                g_misc[0] = logdet;
                g_misc[1] = tr;
            }
        }
        __syncthreads();
        if (threadIdx.x < RK * RK) g_gram[threadIdx.x] = 0.0f;  // reset for replay
        return;
    }

    int tid = blockIdx.x * blockDim.x + threadIdx.x;
    int sub = threadIdx.x & 3;
    int gid = tid >> 2;
    int gstride = (EDGE_BLKS * 256) >> 2;

    int acc0 = 0, acc1 = 0, acc2 = 0, acc3 = 0;
    float aself = 0.0f;

    int iters = (E + gstride - 1) / gstride;
    int U = iters - 1;                 // unguarded iterations
    int it = 0;
    for (; it + 3 < U; it += 4) {
        int e0 = gid + it * gstride;
        int e1 = e0 + gstride, e2 = e1 + gstride, e3 = e2 + gstride;
        int r0 = __ldg(ei + e0), c0 = __ldg(ei + (size_t)E + e0);
        int r1 = __ldg(ei + e1), c1 = __ldg(ei + (size_t)E + e1);
        int r2 = __ldg(ei + e2), c2 = __ldg(ei + (size_t)E + e2);
        int r3 = __ldg(ei + e3), c3 = __ldg(ei + (size_t)E + e3);
        edge_dp(r0, c0, sub, acc0, aself);
        edge_dp(r1, c1, sub, acc1, aself);
        edge_dp(r2, c2, sub, acc2, aself);
        edge_dp(r3, c3, sub, acc3, aself);
    }
    for (; it < U; it++) {
        int e = gid + it * gstride;
        int r = __ldg(ei + e), c = __ldg(ei + (size_t)E + e);
        edge_dp(r, c, sub, acc0, aself);
    }
    {                                  // guarded tail
        int e = gid + U * gstride;
        if (e < E) {
            int r = __ldg(ei + e), c = __ldg(ei + (size_t)E + e);
            edge_dp(r, c, sub, acc1, aself);
        }
    }

    float accD = (float)((acc0 + acc1) + (acc2 + acc3)) * QS2INV;

    // block reduce
    for (int o = 16; o; o >>= 1) {
        accD += __shfl_xor_sync(0xffffffffu, accD, o);
        aself += __shfl_xor_sync(0xffffffffu, aself, o);
    }
    __shared__ float s0[8], s1[8];
    int w = threadIdx.x >> 5, l = threadIdx.x & 31;
    if (l == 0) { s0[w] = accD; s1[w] = aself; }
    __syncthreads();
    if (threadIdx.x == 0) {
        float A = 0.f, B = 0.f;
        for (int i = 0; i < 8; i++) { A += s0[i]; B += s1[i]; }
        atomicAdd(&g_acc[1], (double)A);
        atomicAdd(&g_acc[2], (double)B);
    }
}

// Tiny finalize: combine scalars, write out, reset g_acc/g_misc.
__global__ void k_final(float* out, int N) {
    if (threadIdx.x == 0) {
        double logdet = (double)g_misc[0];
        double tr = (double)g_misc[1];
        double trace_L = (double)N - g_acc[2];
        double res = (g_acc[0] / (double)DM + tr + trace_L - g_acc[1] - logdet)
                     / (2.0 * (double)N);
        out[0] = (float)res;
        g_acc[0] = 0.0; g_acc[1] = 0.0; g_acc[2] = 0.0;
        g_misc[0] = 0.0f; g_misc[1] = 0.0f;
    }
}

// ---------------------------------------------------------------------------
extern "C" void kernel_launch(void* const* d_in, const int* in_sizes, int n_in,
                              void* d_out, int out_size) {
    const float* zm = (const float*)d_in[0];
    const float* zs = (const float*)d_in[1];
    const int*   ei = (const int*)d_in[2];

    int N = in_sizes[0] / DM;
    int E = in_sizes[2] / 2;

    k_deg_gram<<<GRAM_BLKS + 1264, 256>>>(zs, ei, N, E);
    k_pack<<<(N + 31) / 32, 256>>>(zm, zs, N);
    k_edges<<<EDGE_BLKS + 1, 256>>>(ei, E);  // +1 block runs the Cholesky
    k_final<<<1, 32>>>((float*)d_out, N);
}